// round 2
// baseline (speedup 1.0000x reference)
#include <cuda_runtime.h>
#include <cuda_bf16.h>

#define BATCH  4
#define SEQ    2048
#define DMODEL 1024
#define NSTATE 16
#define SEG    64                  // segment length
#define NSEGS  (SEQ / SEG)         // 32 segments
#define SUPER  8                   // segments per super-segment
#define NSUP   (NSEGS / SUPER)     // 4 supers
#define NCH    (BATCH * DMODEL)    // 4096 channels

// ---------------- device scratch (static: no allocation) ----------------
__device__ float g_c[SEG];                    // c_k = b^T A^k b
__device__ float g_vrev[SEG][NSTATE];         // vrev[s] = A^{63-s} b
__device__ float g_Q[SEG][NSTATE];            // Q[r]  = (A^T)^{r+1} b
__device__ float g_A64[NSTATE * NSTATE];      // A^64
__device__ float g_A512[NSTATE * NSTATE];     // A^512
__device__ float g_V[NSEGS][NSTATE][NCH];     // per-segment injected state  (8 MB)
__device__ float g_Vsup[NSUP][NSTATE][NCH];   // per-super injected state    (1 MB)
__device__ float g_Hsup[NSUP][NSTATE][NCH];   // super entry states          (1 MB)
__device__ float g_Hseg[NSEGS][NSTATE][NCH];  // segment entry states        (8 MB)

// ---------------- K0: precompute filter taps and transition powers ----------------
__global__ void __launch_bounds__(256) k0_precompute(const float* __restrict__ A,
                                                     const float* __restrict__ bvec) {
    __shared__ float sA[NSTATE * NSTATE];
    __shared__ float M[2][NSTATE * NSTATE];
    __shared__ float sb[NSTATE];
    const int tid = threadIdx.x;            // 256 threads
    sA[tid] = A[tid];
    if (tid < NSTATE) sb[tid] = bvec[tid];
    M[0][tid] = ((tid >> 4) == (tid & 15)) ? 1.f : 0.f;   // M = I
    __syncthreads();

    int cur = 0;
    const int row = tid >> 4, col = tid & 15;
    for (int j = 0; j < SEG; ++j) {         // at loop top: M[cur] = A^j
        if (tid < NSTATE) {                 // v_j = A^j b  -> vrev[63-j]
            float a = 0.f;
            #pragma unroll
            for (int n = 0; n < NSTATE; ++n) a = fmaf(M[cur][tid * NSTATE + n], sb[n], a);
            g_vrev[SEG - 1 - j][tid] = a;
        } else if (tid < 32 && j >= 1) {    // Q[j-1] = b^T A^j
            const int m = tid - NSTATE;
            float a = 0.f;
            #pragma unroll
            for (int k = 0; k < NSTATE; ++k) a = fmaf(sb[k], M[cur][k * NSTATE + m], a);
            g_Q[j - 1][m] = a;
        }
        // M[1-cur] = M[cur] * A  (reads M[cur], writes other buffer: one barrier/iter)
        float a = 0.f;
        #pragma unroll
        for (int k = 0; k < NSTATE; ++k)
            a = fmaf(M[cur][row * NSTATE + k], sA[k * NSTATE + col], a);
        M[1 - cur][tid] = a;
        __syncthreads();
        cur ^= 1;
    }
    // M[cur] = A^64
    g_A64[tid] = M[cur][tid];
    if (tid < NSTATE) {                     // Q[63] = b^T A^64
        float a = 0.f;
        #pragma unroll
        for (int k = 0; k < NSTATE; ++k) a = fmaf(sb[k], M[cur][k * NSTATE + tid], a);
        g_Q[SEG - 1][tid] = a;
    }
    if (tid < SEG) {                        // c_j = b . v_j  (vrev already global-visible)
        float a = 0.f;
        #pragma unroll
        for (int m = 0; m < NSTATE; ++m) a = fmaf(sb[m], g_vrev[SEG - 1 - tid][m], a);
        g_c[tid] = a;
    }
    // A^512 = (A^64)^(2^3): three squarings
    for (int q = 0; q < 3; ++q) {
        float a = 0.f;
        #pragma unroll
        for (int k = 0; k < NSTATE; ++k)
            a = fmaf(M[cur][row * NSTATE + k], M[cur][k * NSTATE + col], a);
        M[1 - cur][tid] = a;
        __syncthreads();
        cur ^= 1;
    }
    g_A512[tid] = M[cur][tid];
}

// ---------------- K1: per-(channel,segment) local conv + injected state ----------------
__global__ void __launch_bounds__(256) k1_local(const float* __restrict__ x,
                                                float* __restrict__ out) {
    __shared__ float sc[SEG];
    __shared__ float sv[SEG][NSTATE];
    const int tid = threadIdx.x;
    if (tid < SEG) sc[tid] = g_c[tid];
    for (int i = tid; i < SEG * NSTATE; i += 256)
        (&sv[0][0])[i] = (&g_vrev[0][0])[i];
    __syncthreads();

    const int bid = blockIdx.x;             // 512 blocks = 4 d-tiles * 4 batch * 32 segs
    const int d   = (bid & 3) * 256 + tid;
    const int b   = (bid >> 2) & 3;
    const int g   = bid >> 4;

    const size_t base = ((size_t)b * SEQ + (size_t)g * SEG) * DMODEL + d;
    const float* xp = x + base;
    float xs[SEG];
    #pragma unroll
    for (int s = 0; s < SEG; ++s) xs[s] = xp[(size_t)s * DMODEL];

    // triangular local convolution, 16 outputs at a time for ILP
    float* op = out + base;
    #pragma unroll
    for (int rb = 0; rb < SEG; rb += 16) {
        float acc[16];
        #pragma unroll
        for (int i = 0; i < 16; ++i) acc[i] = 0.f;
        #pragma unroll
        for (int s = 0; s < SEG; ++s) {
            if (s >= rb + 16) break;
            const float xv = xs[s];
            #pragma unroll
            for (int i = 0; i < 16; ++i) {
                const int r = rb + i;
                if (s <= r) acc[i] = fmaf(sc[r - s], xv, acc[i]);
            }
        }
        #pragma unroll
        for (int i = 0; i < 16; ++i) op[(size_t)(rb + i) * DMODEL] = acc[i];
    }

    // injected state V = sum_s A^{63-s} b x_s
    float V[NSTATE];
    #pragma unroll
    for (int m = 0; m < NSTATE; ++m) V[m] = 0.f;
    #pragma unroll
    for (int s = 0; s < SEG; ++s) {
        const float xv = xs[s];
        #pragma unroll
        for (int m = 0; m < NSTATE; ++m) V[m] = fmaf(sv[s][m], xv, V[m]);
    }
    const int ch = b * DMODEL + d;
    #pragma unroll
    for (int m = 0; m < NSTATE; ++m) g_V[g][m][ch] = V[m];
}

// ---------------- K2a: Horner-combine 8 segment V's into super V ----------------
__global__ void __launch_bounds__(256) k2a_super(void) {
    __shared__ float sA[NSTATE * NSTATE];
    const int tid = threadIdx.x;
    sA[tid] = g_A64[tid];
    __syncthreads();
    const int job = blockIdx.x * 256 + tid;     // 16384 jobs
    const int ch  = job & (NCH - 1);
    const int sup = job >> 12;
    float W[NSTATE];
    #pragma unroll
    for (int m = 0; m < NSTATE; ++m) W[m] = 0.f;
    for (int i = 0; i < SUPER; ++i) {
        const int g = sup * SUPER + i;
        float nW[NSTATE];
        #pragma unroll
        for (int m = 0; m < NSTATE; ++m) {
            float a = g_V[g][m][ch];
            #pragma unroll
            for (int n = 0; n < NSTATE; ++n) a = fmaf(sA[m * NSTATE + n], W[n], a);
            nW[m] = a;
        }
        #pragma unroll
        for (int m = 0; m < NSTATE; ++m) W[m] = nW[m];
    }
    #pragma unroll
    for (int m = 0; m < NSTATE; ++m) g_Vsup[sup][m][ch] = W[m];
}

// ---------------- K2b: prefix over supers (per channel) ----------------
__global__ void __launch_bounds__(256) k2b_prefix(void) {
    __shared__ float sA[NSTATE * NSTATE];
    const int tid = threadIdx.x;
    sA[tid] = g_A512[tid];
    __syncthreads();
    const int ch = blockIdx.x * 256 + tid;      // 4096 channels
    float H[NSTATE];
    #pragma unroll
    for (int m = 0; m < NSTATE; ++m) H[m] = 0.f;
    for (int s = 0; s < NSUP; ++s) {
        #pragma unroll
        for (int m = 0; m < NSTATE; ++m) g_Hsup[s][m][ch] = H[m];
        if (s < NSUP - 1) {
            float nH[NSTATE];
            #pragma unroll
            for (int m = 0; m < NSTATE; ++m) {
                float a = g_Vsup[s][m][ch];
                #pragma unroll
                for (int n = 0; n < NSTATE; ++n) a = fmaf(sA[m * NSTATE + n], H[n], a);
                nH[m] = a;
            }
            #pragma unroll
            for (int m = 0; m < NSTATE; ++m) H[m] = nH[m];
        }
    }
}

// ---------------- K2c: expand super entry state to every segment entry ----------------
__global__ void __launch_bounds__(256) k2c_expand(void) {
    __shared__ float sA[NSTATE * NSTATE];
    const int tid = threadIdx.x;
    sA[tid] = g_A64[tid];
    __syncthreads();
    const int job = blockIdx.x * 256 + tid;     // 16384 jobs
    const int ch  = job & (NCH - 1);
    const int sup = job >> 12;
    float H[NSTATE];
    #pragma unroll
    for (int m = 0; m < NSTATE; ++m) H[m] = g_Hsup[sup][m][ch];
    for (int i = 0; i < SUPER; ++i) {
        const int g = sup * SUPER + i;
        #pragma unroll
        for (int m = 0; m < NSTATE; ++m) g_Hseg[g][m][ch] = H[m];
        if (i < SUPER - 1) {
            float nH[NSTATE];
            #pragma unroll
            for (int m = 0; m < NSTATE; ++m) {
                float a = g_V[g][m][ch];
                #pragma unroll
                for (int n = 0; n < NSTATE; ++n) a = fmaf(sA[m * NSTATE + n], H[n], a);
                nH[m] = a;
            }
            #pragma unroll
            for (int m = 0; m < NSTATE; ++m) H[m] = nH[m];
        }
    }
}

// ---------------- K3: add entering-state contribution  y += Q[r] . H_seg ----------------
__global__ void __launch_bounds__(256) k3_correct(float* __restrict__ out) {
    __shared__ float sQ[SEG][NSTATE];
    const int tid = threadIdx.x;
    for (int i = tid; i < SEG * NSTATE; i += 256)
        (&sQ[0][0])[i] = (&g_Q[0][0])[i];
    __syncthreads();
    const size_t idx = (size_t)blockIdx.x * 256 + tid;    // 8.4M outputs
    const int d = (int)(idx & (DMODEL - 1));
    const int t = (int)((idx >> 10) & (SEQ - 1));
    const int b = (int)(idx >> 21);
    const int ch = b * DMODEL + d;
    const int g = t >> 6, r = t & (SEG - 1);
    float acc = out[idx];
    #pragma unroll
    for (int m = 0; m < NSTATE; ++m)
        acc = fmaf(sQ[r][m], g_Hseg[g][m][ch], acc);
    out[idx] = acc;
}

// ---------------- launch ----------------
extern "C" void kernel_launch(void* const* d_in, const int* in_sizes, int n_in,
                              void* d_out, int out_size) {
    const float* x = nullptr; const float* A = nullptr; const float* bv = nullptr;
    for (int i = 0; i < n_in; ++i) {
        if      (in_sizes[i] == BATCH * SEQ * DMODEL) x  = (const float*)d_in[i];
        else if (in_sizes[i] == NSTATE * NSTATE)      A  = (const float*)d_in[i];
        else if (in_sizes[i] == NSTATE)               bv = (const float*)d_in[i];
    }
    float* out = (float*)d_out;

    k0_precompute<<<1, 256>>>(A, bv);
    k1_local<<<(DMODEL / 256) * BATCH * NSEGS, 256>>>(x, out);   // 512 blocks
    k2a_super<<<(NSUP * NCH) / 256, 256>>>();                    // 64 blocks
    k2b_prefix<<<NCH / 256, 256>>>();                            // 16 blocks
    k2c_expand<<<(NSUP * NCH) / 256, 256>>>();                   // 64 blocks
    k3_correct<<<(BATCH * SEQ * DMODEL) / 256, 256>>>(out);      // 32768 blocks
}